// round 4
// baseline (speedup 1.0000x reference)
#include <cuda_runtime.h>
#include <math.h>

// Problem constants: N_OBJ=1024, C_DET=8, C_SEG=4, H=W=28
#define C_DET 8
#define C_SEG 4
#define HW 784
#define HW4 196          // HW / 4 (float4 units)
#define N_OBJ 1024
#define NB 8             // objects per block
#define NCHUNK (N_OBJ / NB)   // 128
#define RTHREADS 256
#define NBLOCKS (NCHUNK * C_DET)  // 1024

// Per-block partial sums, k-major for coalesced tail reads:
// k=0: denom, k=1..4: overlap with seg class 0..3.
// Fully overwritten every launch -> no zeroing, graph-replay safe.
__device__ float g_part[5][C_DET][NCHUNK];
__device__ unsigned int g_count;  // ticket; reset by last block each launch

__global__ __launch_bounds__(RTHREADS) void fused_kernel(
    const float4* __restrict__ det4,   // (N,C_DET,HW4) float4
    const float4* __restrict__ seg4,   // (N,C_DET,C_SEG,HW4) float4
    const float*  __restrict__ dcp,    // (N_OBJ, C_DET)
    const int*    __restrict__ edge_i, // int32
    const int*    __restrict__ edge_j,
    int n_edges,
    float* __restrict__ out)
{
    const int c  = blockIdx.y;
    const int n0 = blockIdx.x * NB;
    const int tid = threadIdx.x;

    // ---------- Phase A: streaming reduction (the 128.5 MB scan) ----------
    float dsum = 0.0f;
    float a0 = 0.0f, a1 = 0.0f, a2 = 0.0f, a3 = 0.0f;

    for (int t = tid; t < NB * HW4; t += RTHREADS) {
        const int nl = t / HW4;
        const int q  = t - nl * HW4;
        const long m = (long)(n0 + nl) * C_DET + c;

        const float4 d = det4[m * HW4 + q];
        dsum += (d.x + d.y) + (d.z + d.w);

        const long sb = m * (C_SEG * HW4) + q;
        float4 v;
        v = seg4[sb + 0 * HW4]; a0 += d.x * v.x + d.y * v.y + d.z * v.z + d.w * v.w;
        v = seg4[sb + 1 * HW4]; a1 += d.x * v.x + d.y * v.y + d.z * v.z + d.w * v.w;
        v = seg4[sb + 2 * HW4]; a2 += d.x * v.x + d.y * v.y + d.z * v.z + d.w * v.w;
        v = seg4[sb + 3 * HW4]; a3 += d.x * v.x + d.y * v.y + d.z * v.z + d.w * v.w;
    }

    #pragma unroll
    for (int off = 16; off; off >>= 1) {
        dsum += __shfl_xor_sync(0xFFFFFFFFu, dsum, off);
        a0   += __shfl_xor_sync(0xFFFFFFFFu, a0, off);
        a1   += __shfl_xor_sync(0xFFFFFFFFu, a1, off);
        a2   += __shfl_xor_sync(0xFFFFFFFFu, a2, off);
        a3   += __shfl_xor_sync(0xFFFFFFFFu, a3, off);
    }

    __shared__ float sm[5][RTHREADS / 32];
    const int wid = tid >> 5;
    const int lid = tid & 31;
    if (lid == 0) {
        sm[0][wid] = dsum; sm[1][wid] = a0; sm[2][wid] = a1;
        sm[3][wid] = a2;   sm[4][wid] = a3;
    }
    __syncthreads();

    if (tid == 0) {
        float r[5] = {0, 0, 0, 0, 0};
        #pragma unroll
        for (int w = 0; w < RTHREADS / 32; w++) {
            r[0] += sm[0][w]; r[1] += sm[1][w]; r[2] += sm[2][w];
            r[3] += sm[3][w]; r[4] += sm[4][w];
        }
        #pragma unroll
        for (int k = 0; k < 5; k++) g_part[k][c][blockIdx.x] = r[k];
    }

    // ---------- Ticket: last block does the tail ----------
    __threadfence();
    __shared__ unsigned int s_last;
    if (tid == 0) {
        unsigned int old = atomicAdd(&g_count, 1u);
        s_last = (old == NBLOCKS - 1) ? 1u : 0u;
    }
    __syncthreads();
    if (!s_last) return;
    if (tid == 0) g_count = 0;  // reset for next graph replay

    // ---------- Phase B: sum partials (deterministic, one warp per class) ----------
    __shared__ double s_acc[C_DET][5];
    __shared__ float  s_w[C_DET];
    __shared__ float  s_red[RTHREADS / 32];

    // warp w handles class c=w; iterates k=0..4 over its 128 partials.
    {
        const int cc = wid;  // 8 warps, 8 classes
        #pragma unroll
        for (int k = 0; k < 5; k++) {
            const float* p = g_part[k][cc];
            double s = (double)p[lid] + (double)p[lid + 32]
                     + (double)p[lid + 64] + (double)p[lid + 96];
            #pragma unroll
            for (int off = 16; off; off >>= 1)
                s += __shfl_xor_sync(0xFFFFFFFFu, s, off);
            if (lid == 0) s_acc[cc][k] = s;
        }
    }
    __syncthreads();

    // ---------- Phase C: edge weights (atomic-free, deterministic) ----------
    if (tid < C_DET) {
        double acc = 0.0;
        for (int e = 0; e < n_edges; e++) {
            if (edge_j[e] == tid)
                acc += s_acc[tid][1 + edge_i[e]] / s_acc[tid][0];
        }
        s_w[tid] = (float)acc;
    }
    __syncthreads();

    // ---------- Phase D: per-object prob + BCE mean ----------
    float w[C_DET];
    #pragma unroll
    for (int k = 0; k < C_DET; k++) w[k] = s_w[k];

    const float4* dcp4 = (const float4*)dcp;
    float l = 0.0f;
    #pragma unroll
    for (int o = 0; o < N_OBJ / RTHREADS; o++) {
        const int obj = o * RTHREADS + tid;
        const float4 d0 = dcp4[obj * 2 + 0];
        const float4 d1 = dcp4[obj * 2 + 1];
        float p = d0.x * w[0] + d0.y * w[1] + d0.z * w[2] + d0.w * w[3]
                + d1.x * w[4] + d1.y * w[5] + d1.z * w[6] + d1.w * w[7];
        l += -fmaxf(logf(p), -100.0f);
    }

    #pragma unroll
    for (int off = 16; off; off >>= 1) l += __shfl_xor_sync(0xFFFFFFFFu, l, off);
    if (lid == 0) s_red[wid] = l;
    __syncthreads();

    if (tid == 0) {
        float v = 0.0f;
        #pragma unroll
        for (int i = 0; i < RTHREADS / 32; i++) v += s_red[i];
        out[0] = v / (float)N_OBJ;
    }
}

extern "C" void kernel_launch(void* const* d_in, const int* in_sizes, int n_in,
                              void* d_out, int out_size) {
    // metadata order: det_class_probs (f32), det_mask_probs (f32),
    //                 seg_mask_probs (f32), edge_i (i32), edge_j (i32)
    const float*  dcp = (const float*)d_in[0];
    const float4* det = (const float4*)d_in[1];
    const float4* seg = (const float4*)d_in[2];
    const int*    ei  = (const int*)d_in[3];
    const int*    ej  = (const int*)d_in[4];
    const int n_edges = in_sizes[3];
    float* out = (float*)d_out;

    fused_kernel<<<dim3(NCHUNK, C_DET), RTHREADS>>>(det, seg, dcp, ei, ej, n_edges, out);
}

// round 5
// speedup vs baseline: 1.0476x; 1.0476x over previous
#include <cuda_runtime.h>
#include <math.h>

// Problem constants: N_OBJ=1024, C_DET=8, C_SEG=4, H=W=28
#define C_DET 8
#define C_SEG 4
#define HW 784
#define HW4 196          // HW / 4 (float4 units)
#define N_OBJ 1024
#define NB 8             // objects per block (one per warp)
#define NCHUNK (N_OBJ / NB)   // 128
#define RTHREADS 256
#define NITER ((HW4 + 31) / 32)   // 7

// Per-block partial sums, k-major for coalesced finalize reads.
// k=0: denom, k=1..4: overlap with seg class 0..3.
// Fully overwritten every launch -> no zeroing, graph-replay safe.
__device__ float g_part[5][C_DET][NCHUNK];

// Streaming reduction: block=(chunk, det class), warp=object.
// Each thread: up to 7 quads x (1 det4 + 4 seg4) independent streaming loads.
__global__ __launch_bounds__(RTHREADS) void reduce_kernel(
    const float4* __restrict__ det4,   // (N,C_DET,HW4) float4
    const float4* __restrict__ seg4)   // (N,C_DET,C_SEG,HW4) float4
{
    const int c   = blockIdx.y;
    const int wid = threadIdx.x >> 5;
    const int lid = threadIdx.x & 31;
    const int n   = blockIdx.x * NB + wid;

    const long mb = (long)n * C_DET + c;
    const float4* __restrict__ dp = det4 + mb * HW4;
    const float4* __restrict__ sp = seg4 + mb * (C_SEG * HW4);

    float dsum = 0.0f;
    float a0 = 0.0f, a1 = 0.0f, a2 = 0.0f, a3 = 0.0f;

    #pragma unroll
    for (int it = 0; it < NITER; it++) {
        const int q = lid + it * 32;
        if (q < HW4) {
            const float4 d  = __ldcs(dp + q);
            const float4 s0 = __ldcs(sp + 0 * HW4 + q);
            const float4 s1 = __ldcs(sp + 1 * HW4 + q);
            const float4 s2 = __ldcs(sp + 2 * HW4 + q);
            const float4 s3 = __ldcs(sp + 3 * HW4 + q);
            dsum += (d.x + d.y) + (d.z + d.w);
            a0 += d.x * s0.x + d.y * s0.y + d.z * s0.z + d.w * s0.w;
            a1 += d.x * s1.x + d.y * s1.y + d.z * s1.z + d.w * s1.w;
            a2 += d.x * s2.x + d.y * s2.y + d.z * s2.z + d.w * s2.w;
            a3 += d.x * s3.x + d.y * s3.y + d.z * s3.z + d.w * s3.w;
        }
    }

    // Warp reduce 5 scalars
    #pragma unroll
    for (int off = 16; off; off >>= 1) {
        dsum += __shfl_xor_sync(0xFFFFFFFFu, dsum, off);
        a0   += __shfl_xor_sync(0xFFFFFFFFu, a0, off);
        a1   += __shfl_xor_sync(0xFFFFFFFFu, a1, off);
        a2   += __shfl_xor_sync(0xFFFFFFFFu, a2, off);
        a3   += __shfl_xor_sync(0xFFFFFFFFu, a3, off);
    }

    __shared__ float sm[5][RTHREADS / 32];
    if (lid == 0) {
        sm[0][wid] = dsum; sm[1][wid] = a0; sm[2][wid] = a1;
        sm[3][wid] = a2;   sm[4][wid] = a3;
    }
    __syncthreads();

    if (threadIdx.x < 5) {          // 5 threads each sum 8 warp values, 1 STG each
        const int k = threadIdx.x;
        float r = 0.0f;
        #pragma unroll
        for (int w = 0; w < RTHREADS / 32; w++) r += sm[k][w];
        g_part[k][c][blockIdx.x] = r;
    }
}

// One block of 1024 threads: sum partials (coalesced, deterministic),
// edge weights, per-object probs, BCE(target=1) = mean(-max(log p, -100)).
__global__ __launch_bounds__(N_OBJ) void finalize_kernel(
    const float* __restrict__ dcp,       // (N_OBJ, C_DET)
    const int* __restrict__ edge_i,      // int32
    const int* __restrict__ edge_j,
    int n_edges,
    float* __restrict__ out)
{
    __shared__ float  sm2[C_DET][5][4];   // per-warp partials within each class group
    __shared__ double s_acc[C_DET][5];
    __shared__ float  s_w[C_DET];
    __shared__ float  red[N_OBJ / 32];
    const int t = threadIdx.x;
    const int lid = t & 31;

    // Phase 1: group g = t>>7 handles class c=g; chunk = t&127.
    {
        const int c = t >> 7;
        const int chunk = t & 127;
        const int gw = (t >> 5) & 3;      // warp within group
        float v[5];
        #pragma unroll
        for (int k = 0; k < 5; k++) v[k] = g_part[k][c][chunk];  // coalesced
        #pragma unroll
        for (int off = 16; off; off >>= 1) {
            #pragma unroll
            for (int k = 0; k < 5; k++)
                v[k] += __shfl_xor_sync(0xFFFFFFFFu, v[k], off);
        }
        if (lid == 0) {
            #pragma unroll
            for (int k = 0; k < 5; k++) sm2[c][k][gw] = v[k];
        }
    }
    __syncthreads();

    if (t < C_DET * 5) {                 // fixed-order double combine: deterministic
        const int c = t / 5, k = t - 5 * c;
        s_acc[c][k] = ((double)sm2[c][k][0] + (double)sm2[c][k][1])
                    + ((double)sm2[c][k][2] + (double)sm2[c][k][3]);
    }
    __syncthreads();

    // Phase 2: edge weights (atomic-free, thread j scans all edges)
    if (t < C_DET) {
        double acc = 0.0;
        for (int e = 0; e < n_edges; e++)
            if (edge_j[e] == t)
                acc += s_acc[t][1 + edge_i[e]] / s_acc[t][0];
        s_w[t] = (float)acc;
    }
    __syncthreads();

    // Phase 3: per-object prob + BCE mean (one object per thread)
    float w[C_DET];
    #pragma unroll
    for (int k = 0; k < C_DET; k++) w[k] = s_w[k];

    const float4* dcp4 = (const float4*)dcp;
    const float4 d0 = dcp4[t * 2 + 0];
    const float4 d1 = dcp4[t * 2 + 1];
    float p = d0.x * w[0] + d0.y * w[1] + d0.z * w[2] + d0.w * w[3]
            + d1.x * w[4] + d1.y * w[5] + d1.z * w[6] + d1.w * w[7];
    float l = -fmaxf(logf(p), -100.0f);

    #pragma unroll
    for (int off = 16; off; off >>= 1) l += __shfl_xor_sync(0xFFFFFFFFu, l, off);
    if (lid == 0) red[t >> 5] = l;
    __syncthreads();

    if (t < 32) {
        float v = red[t];
        #pragma unroll
        for (int off = 16; off; off >>= 1) v += __shfl_xor_sync(0xFFFFFFFFu, v, off);
        if (t == 0) out[0] = v / (float)N_OBJ;
    }
}

extern "C" void kernel_launch(void* const* d_in, const int* in_sizes, int n_in,
                              void* d_out, int out_size) {
    // metadata order: det_class_probs (f32), det_mask_probs (f32),
    //                 seg_mask_probs (f32), edge_i (i32), edge_j (i32)
    const float*  dcp = (const float*)d_in[0];
    const float4* det = (const float4*)d_in[1];
    const float4* seg = (const float4*)d_in[2];
    const int*    ei  = (const int*)d_in[3];
    const int*    ej  = (const int*)d_in[4];
    const int n_edges = in_sizes[3];
    float* out = (float*)d_out;

    reduce_kernel<<<dim3(NCHUNK, C_DET), RTHREADS>>>(det, seg);
    finalize_kernel<<<1, N_OBJ>>>(dcp, ei, ej, n_edges, out);
}

// round 6
// speedup vs baseline: 1.1159x; 1.0652x over previous
#include <cuda_runtime.h>
#include <math.h>

// Problem constants: N_OBJ=1024, C_DET=8, C_SEG=4, H=W=28
#define C_DET 8
#define C_SEG 4
#define HW 784
#define HW4 196          // HW / 4 (float4 units)
#define N_OBJ 1024
#define NB 8             // objects per block (one per warp)
#define NCHUNK (N_OBJ / NB)   // 128
#define RTHREADS 256
#define NITER ((HW4 + 31) / 32)   // 7
#define MAX_EDGES 64

// Per-block partial sums, k-major for coalesced finalize reads.
// k=0: denom, k=1..4: overlap with seg class 0..3.
// Fully overwritten every launch -> no zeroing, graph-replay safe.
__device__ float g_part[5][C_DET][NCHUNK];

// Streaming reduction: block=(chunk, det class), warp=object.
__global__ __launch_bounds__(RTHREADS) void reduce_kernel(
    const float4* __restrict__ det4,   // (N,C_DET,HW4) float4
    const float4* __restrict__ seg4)   // (N,C_DET,C_SEG,HW4) float4
{
    const int c   = blockIdx.y;
    const int wid = threadIdx.x >> 5;
    const int lid = threadIdx.x & 31;
    const int n   = blockIdx.x * NB + wid;

    const long mb = (long)n * C_DET + c;
    const float4* __restrict__ dp = det4 + mb * HW4;
    const float4* __restrict__ sp = seg4 + mb * (C_SEG * HW4);

    float dsum = 0.0f;
    float a0 = 0.0f, a1 = 0.0f, a2 = 0.0f, a3 = 0.0f;

    #pragma unroll
    for (int it = 0; it < NITER; it++) {
        const int q = lid + it * 32;
        if (q < HW4) {
            const float4 d  = __ldcs(dp + q);
            const float4 s0 = __ldcs(sp + 0 * HW4 + q);
            const float4 s1 = __ldcs(sp + 1 * HW4 + q);
            const float4 s2 = __ldcs(sp + 2 * HW4 + q);
            const float4 s3 = __ldcs(sp + 3 * HW4 + q);
            dsum += (d.x + d.y) + (d.z + d.w);
            a0 += d.x * s0.x + d.y * s0.y + d.z * s0.z + d.w * s0.w;
            a1 += d.x * s1.x + d.y * s1.y + d.z * s1.z + d.w * s1.w;
            a2 += d.x * s2.x + d.y * s2.y + d.z * s2.z + d.w * s2.w;
            a3 += d.x * s3.x + d.y * s3.y + d.z * s3.z + d.w * s3.w;
        }
    }

    #pragma unroll
    for (int off = 16; off; off >>= 1) {
        dsum += __shfl_xor_sync(0xFFFFFFFFu, dsum, off);
        a0   += __shfl_xor_sync(0xFFFFFFFFu, a0, off);
        a1   += __shfl_xor_sync(0xFFFFFFFFu, a1, off);
        a2   += __shfl_xor_sync(0xFFFFFFFFu, a2, off);
        a3   += __shfl_xor_sync(0xFFFFFFFFu, a3, off);
    }

    __shared__ float sm[5][RTHREADS / 32];
    if (lid == 0) {
        sm[0][wid] = dsum; sm[1][wid] = a0; sm[2][wid] = a1;
        sm[3][wid] = a2;   sm[4][wid] = a3;
    }
    __syncthreads();

    if (threadIdx.x < 5) {
        const int k = threadIdx.x;
        float r = 0.0f;
        #pragma unroll
        for (int w = 0; w < RTHREADS / 32; w++) r += sm[k][w];
        g_part[k][c][blockIdx.x] = r;
    }
}

// One block of 1024 threads. All global loads are issued in parallel up front
// (one DRAM latency round each); no serialized global loops anywhere.
__global__ __launch_bounds__(N_OBJ) void finalize_kernel(
    const float* __restrict__ dcp,       // (N_OBJ, C_DET)
    const int* __restrict__ edge_i,      // int32
    const int* __restrict__ edge_j,
    int n_edges,
    float* __restrict__ out)
{
    __shared__ float  sm2[C_DET][5][4];
    __shared__ double s_acc[C_DET][5];
    __shared__ float  s_w[C_DET];
    __shared__ float  red[N_OBJ / 32];
    __shared__ int    s_ei[MAX_EDGES], s_ej[MAX_EDGES];
    const int t = threadIdx.x;
    const int lid = t & 31;

    // Parallel edge load: one thread per edge (single latency round,
    // overlapped with dcp/g_part loads below).
    if (t < n_edges) { s_ei[t] = edge_i[t]; s_ej[t] = edge_j[t]; }

    // Prefetch this thread's dcp row early (DRAM round overlaps everything).
    const float4* dcp4 = (const float4*)dcp;
    const float4 d0 = dcp4[t * 2 + 0];
    const float4 d1 = dcp4[t * 2 + 1];

    // Phase 1: group g = t>>7 handles class c=g; chunk = t&127.
    {
        const int c = t >> 7;
        const int chunk = t & 127;
        const int gw = (t >> 5) & 3;
        float v[5];
        #pragma unroll
        for (int k = 0; k < 5; k++) v[k] = g_part[k][c][chunk];  // coalesced
        #pragma unroll
        for (int off = 16; off; off >>= 1) {
            #pragma unroll
            for (int k = 0; k < 5; k++)
                v[k] += __shfl_xor_sync(0xFFFFFFFFu, v[k], off);
        }
        if (lid == 0) {
            #pragma unroll
            for (int k = 0; k < 5; k++) sm2[c][k][gw] = v[k];
        }
    }
    __syncthreads();

    if (t < C_DET * 5) {                 // fixed-order double combine: deterministic
        const int c = t / 5, k = t - 5 * c;
        s_acc[c][k] = ((double)sm2[c][k][0] + (double)sm2[c][k][1])
                    + ((double)sm2[c][k][2] + (double)sm2[c][k][3]);
    }
    __syncthreads();

    // Phase 2: edge weights from SHARED indices (fast, deterministic).
    if (t < C_DET) {
        double acc = 0.0;
        for (int e = 0; e < n_edges; e++)
            if (s_ej[e] == t)
                acc += s_acc[t][1 + s_ei[e]] / s_acc[t][0];
        s_w[t] = (float)acc;
    }
    __syncthreads();

    // Phase 3: per-object prob + BCE mean (one object per thread).
    float w[C_DET];
    #pragma unroll
    for (int k = 0; k < C_DET; k++) w[k] = s_w[k];

    float p = d0.x * w[0] + d0.y * w[1] + d0.z * w[2] + d0.w * w[3]
            + d1.x * w[4] + d1.y * w[5] + d1.z * w[6] + d1.w * w[7];
    float l = -fmaxf(logf(p), -100.0f);

    #pragma unroll
    for (int off = 16; off; off >>= 1) l += __shfl_xor_sync(0xFFFFFFFFu, l, off);
    if (lid == 0) red[t >> 5] = l;
    __syncthreads();

    if (t < 32) {
        float v = red[t];
        #pragma unroll
        for (int off = 16; off; off >>= 1) v += __shfl_xor_sync(0xFFFFFFFFu, v, off);
        if (t == 0) out[0] = v / (float)N_OBJ;
    }
}

extern "C" void kernel_launch(void* const* d_in, const int* in_sizes, int n_in,
                              void* d_out, int out_size) {
    // metadata order: det_class_probs (f32), det_mask_probs (f32),
    //                 seg_mask_probs (f32), edge_i (i32), edge_j (i32)
    const float*  dcp = (const float*)d_in[0];
    const float4* det = (const float4*)d_in[1];
    const float4* seg = (const float4*)d_in[2];
    const int*    ei  = (const int*)d_in[3];
    const int*    ej  = (const int*)d_in[4];
    const int n_edges = in_sizes[3] < MAX_EDGES ? in_sizes[3] : MAX_EDGES;
    float* out = (float*)d_out;

    reduce_kernel<<<dim3(NCHUNK, C_DET), RTHREADS>>>(det, seg);
    finalize_kernel<<<1, N_OBJ>>>(dcp, ei, ej, n_edges, out);
}

// round 7
// speedup vs baseline: 1.1846x; 1.0615x over previous
#include <cuda_runtime.h>
#include <math.h>

// Problem constants: N_OBJ=1024, C_DET=8, C_SEG=4, H=W=28
#define C_DET 8
#define C_SEG 4
#define HW 784
#define HW4 196          // HW / 4 (float4 units)
#define N_OBJ 1024
#define NB 8             // objects per block (one per warp)
#define NCHUNK (N_OBJ / NB)   // 128
#define RTHREADS 256
#define NITER ((HW4 + 31) / 32)   // 7
#define MAX_EDGES 64

// Per-block partial sums, k-major for coalesced finalize reads.
// Fully overwritten every launch -> no zeroing, graph-replay safe.
__device__ float g_part[5][C_DET][NCHUNK];
__device__ float g_sink;   // DCE-blocker for the L2 warm-up

// Streaming reduction: block=(chunk, det class), warp=object.
// __launch_bounds__(256,7): <=36 regs -> 7 blocks/SM -> 1036 slots >= 1024
// blocks -> SINGLE WAVE (previously 44 regs -> 5 blocks/SM -> 1.38 waves).
__global__ __launch_bounds__(RTHREADS, 7) void reduce_kernel(
    const float4* __restrict__ det4,   // (N,C_DET,HW4) float4
    const float4* __restrict__ seg4,   // (N,C_DET,C_SEG,HW4) float4
    const float4* __restrict__ dcp4,   // (N_OBJ, C_DET) as float4
    const int*    __restrict__ edge_i,
    const int*    __restrict__ edge_j,
    int n_edges)
{
    const int c   = blockIdx.y;
    const int wid = threadIdx.x >> 5;
    const int lid = threadIdx.x & 31;
    const int n   = blockIdx.x * NB + wid;

    const size_t mb = (size_t)n * C_DET + c;
    const float4* __restrict__ dp = det4 + mb * HW4;
    const float4* __restrict__ sp = seg4 + mb * (C_SEG * HW4);

    float dsum = 0.0f;
    float a0 = 0.0f, a1 = 0.0f, a2 = 0.0f, a3 = 0.0f;

    #pragma unroll
    for (int it = 0; it < NITER; it++) {
        const int q = lid + it * 32;
        if (q < HW4) {
            const float4 d  = __ldcs(dp + q);
            const float4 s0 = __ldcs(sp + 0 * HW4 + q);
            const float4 s1 = __ldcs(sp + 1 * HW4 + q);
            const float4 s2 = __ldcs(sp + 2 * HW4 + q);
            const float4 s3 = __ldcs(sp + 3 * HW4 + q);
            dsum += (d.x + d.y) + (d.z + d.w);
            a0 += d.x * s0.x + d.y * s0.y + d.z * s0.z + d.w * s0.w;
            a1 += d.x * s1.x + d.y * s1.y + d.z * s1.z + d.w * s1.w;
            a2 += d.x * s2.x + d.y * s2.y + d.z * s2.z + d.w * s2.w;
            a3 += d.x * s3.x + d.y * s3.y + d.z * s3.z + d.w * s3.w;
        }
    }

    #pragma unroll
    for (int off = 16; off; off >>= 1) {
        dsum += __shfl_xor_sync(0xFFFFFFFFu, dsum, off);
        a0   += __shfl_xor_sync(0xFFFFFFFFu, a0, off);
        a1   += __shfl_xor_sync(0xFFFFFFFFu, a1, off);
        a2   += __shfl_xor_sync(0xFFFFFFFFu, a2, off);
        a3   += __shfl_xor_sync(0xFFFFFFFFu, a3, off);
    }

    __shared__ float sm[5][RTHREADS / 32];
    if (lid == 0) {
        sm[0][wid] = dsum; sm[1][wid] = a0; sm[2][wid] = a1;
        sm[3][wid] = a2;   sm[4][wid] = a3;
    }
    __syncthreads();

    if (threadIdx.x < 5) {
        const int k = threadIdx.x;
        float r = 0.0f;
        #pragma unroll
        for (int w = 0; w < RTHREADS / 32; w++) r += sm[k][w];
        g_part[k][c][blockIdx.x] = r;
    }

    // L2 warm-up for finalize (one block): pull dcp + edges into L2 with
    // default policy; the .cs stream (evict-first) won't evict them.
    if (blockIdx.x == 0 && c == 0) {
        float acc = 0.0f;
        for (int i = threadIdx.x; i < N_OBJ * C_DET / 4; i += RTHREADS) {
            const float4 v = __ldcg(dcp4 + i);
            acc += v.x + v.y + v.z + v.w;
        }
        if (threadIdx.x < n_edges)
            acc += (float)(__ldcg(edge_i + threadIdx.x) + __ldcg(edge_j + threadIdx.x));
        if (threadIdx.x == 0) g_sink = acc;  // deterministic overwrite
    }
}

// One block of 1024 threads. All global loads issued in parallel up front.
__global__ __launch_bounds__(N_OBJ) void finalize_kernel(
    const float* __restrict__ dcp,       // (N_OBJ, C_DET)
    const int* __restrict__ edge_i,      // int32
    const int* __restrict__ edge_j,
    int n_edges,
    float* __restrict__ out)
{
    __shared__ float  sm2[C_DET][5][4];
    __shared__ double s_acc[C_DET][5];
    __shared__ float  s_w[C_DET];
    __shared__ float  red[N_OBJ / 32];
    __shared__ int    s_ei[MAX_EDGES], s_ej[MAX_EDGES];
    const int t = threadIdx.x;
    const int lid = t & 31;

    // Parallel edge load (L2-warm): one thread per edge.
    if (t < n_edges) { s_ei[t] = edge_i[t]; s_ej[t] = edge_j[t]; }

    // Prefetch this thread's dcp row early (L2-warm).
    const float4* dcp4 = (const float4*)dcp;
    const float4 d0 = dcp4[t * 2 + 0];
    const float4 d1 = dcp4[t * 2 + 1];

    // Phase 1: group g = t>>7 handles class c=g; chunk = t&127.
    {
        const int c = t >> 7;
        const int chunk = t & 127;
        const int gw = (t >> 5) & 3;
        float v[5];
        #pragma unroll
        for (int k = 0; k < 5; k++) v[k] = g_part[k][c][chunk];  // coalesced, L2-hit
        #pragma unroll
        for (int off = 16; off; off >>= 1) {
            #pragma unroll
            for (int k = 0; k < 5; k++)
                v[k] += __shfl_xor_sync(0xFFFFFFFFu, v[k], off);
        }
        if (lid == 0) {
            #pragma unroll
            for (int k = 0; k < 5; k++) sm2[c][k][gw] = v[k];
        }
    }
    __syncthreads();

    if (t < C_DET * 5) {                 // fixed-order double combine: deterministic
        const int c = t / 5, k = t - 5 * c;
        s_acc[c][k] = ((double)sm2[c][k][0] + (double)sm2[c][k][1])
                    + ((double)sm2[c][k][2] + (double)sm2[c][k][3]);
    }
    __syncthreads();

    // Phase 2: edge weights from SHARED indices (deterministic, atomic-free).
    if (t < C_DET) {
        double acc = 0.0;
        for (int e = 0; e < n_edges; e++)
            if (s_ej[e] == t)
                acc += s_acc[t][1 + s_ei[e]] / s_acc[t][0];
        s_w[t] = (float)acc;
    }
    __syncthreads();

    // Phase 3: per-object prob + BCE mean (one object per thread).
    float w[C_DET];
    #pragma unroll
    for (int k = 0; k < C_DET; k++) w[k] = s_w[k];

    float p = d0.x * w[0] + d0.y * w[1] + d0.z * w[2] + d0.w * w[3]
            + d1.x * w[4] + d1.y * w[5] + d1.z * w[6] + d1.w * w[7];
    float l = -fmaxf(logf(p), -100.0f);

    #pragma unroll
    for (int off = 16; off; off >>= 1) l += __shfl_xor_sync(0xFFFFFFFFu, l, off);
    if (lid == 0) red[t >> 5] = l;
    __syncthreads();

    if (t < 32) {
        float v = red[t];
        #pragma unroll
        for (int off = 16; off; off >>= 1) v += __shfl_xor_sync(0xFFFFFFFFu, v, off);
        if (t == 0) out[0] = v / (float)N_OBJ;
    }
}

extern "C" void kernel_launch(void* const* d_in, const int* in_sizes, int n_in,
                              void* d_out, int out_size) {
    // metadata order: det_class_probs (f32), det_mask_probs (f32),
    //                 seg_mask_probs (f32), edge_i (i32), edge_j (i32)
    const float*  dcp = (const float*)d_in[0];
    const float4* det = (const float4*)d_in[1];
    const float4* seg = (const float4*)d_in[2];
    const int*    ei  = (const int*)d_in[3];
    const int*    ej  = (const int*)d_in[4];
    const int n_edges = in_sizes[3] < MAX_EDGES ? in_sizes[3] : MAX_EDGES;
    float* out = (float*)d_out;

    reduce_kernel<<<dim3(NCHUNK, C_DET), RTHREADS>>>(det, seg, (const float4*)dcp, ei, ej, n_edges);
    finalize_kernel<<<1, N_OBJ>>>(dcp, ei, ej, n_edges, out);
}